// round 6
// baseline (speedup 1.0000x reference)
#include <cuda_runtime.h>
#include <math.h>

// Shapes fixed by setup_inputs: B=512, N=199, F=64, H=4, U=64
#define BB   512
#define NN   199
#define NP   200
#define FF   64
#define HH   4
#define UU   64
#define MT   64
#define COUT (HH*UU + NN)        // 455
#define NTHR 512

#define FT_STRIDE 68             // feat tile row stride (mult of 4; 68%32=4 -> distinct banks/row)
#define KS_STRIDE 208            // kernels row stride (zero-padded cols 199..207)
#define DT_STRIDE 212            // AWT-stage / dense / mask tile stride (mult of 4)
#define NT_STRIDE 68             // node tile stride

// AWT[h][m][n] = A[n][m] * params[h][n][m], col 199 zero. 640KB, L2-resident.
__device__ float g_AWT[HH * NN * NP];

__global__ void awt_kernel(const float* __restrict__ A, const float* __restrict__ P) {
    int m = blockIdx.x, h = blockIdx.y;
    for (int n = threadIdx.x; n < NP; n += blockDim.x) {
        float v = 0.f;
        if (n < NN) v = A[n * NN + m] * P[((size_t)h * NN + n) * NN + m];
        g_AWT[((size_t)h * NN + m) * NP + n] = v;
    }
}

// SMEM (floats): Xs 12800 + Ft 4352 + Ks 13312 + fcS 4096 + Dt 13568 + Nt 4352 = 52480 -> 209920 B
#define SMEM_FLOATS (NP*FF + MT*FT_STRIDE + FF*KS_STRIDE + FF*UU + MT*DT_STRIDE + MT*NT_STRIDE)

// 8 FMAs: acc pair (a0,a1) += s * (v0,v1)
#define FMA8(a0, a1, s, v0, v1)                                   \
    a0.x = fmaf(s, v0.x, a0.x); a0.y = fmaf(s, v0.y, a0.y);       \
    a0.z = fmaf(s, v0.z, a0.z); a0.w = fmaf(s, v0.w, a0.w);       \
    a1.x = fmaf(s, v1.x, a1.x); a1.y = fmaf(s, v1.y, a1.y);       \
    a1.z = fmaf(s, v1.z, a1.z); a1.w = fmaf(s, v1.w, a1.w);

__global__ __launch_bounds__(NTHR, 1)
void gc_kernel(const float* __restrict__ X, const float* __restrict__ A,
               const float* __restrict__ Kg, const float* __restrict__ FCg,
               const float* __restrict__ b1, const float* __restrict__ b2,
               float* __restrict__ out) {
    extern __shared__ float sm[];
    float* Xs  = sm;                        // [200][64]  X_b, row 199 zeroed
    float* Ft  = Xs + NP * FF;              // [64][68]   feat tile
    float* Ks  = Ft + MT * FT_STRIDE;       // [64][208]  kernels_h (cols >=199 zero)
    float* fcS = Ks + FF * KS_STRIDE;       // [64][64]
    float* Dt  = fcS + FF * UU;             // [64][212]  AWT stage -> dense -> mask
    float* Nt  = Dt + MT * DT_STRIDE;       // [64][68]   node tile

    const int b = blockIdx.x, h = blockIdx.y;
    const int tid  = threadIdx.x;
    const int lane = tid & 31, wid = tid >> 5;
    const int jf4  = (tid & 7) * 4;         // col group base (two float4: jf4, 32+jf4)
    const int row8 = tid >> 3;              // 0..63: one output row per thread (8 threads/row)

    // ---- stage inputs ----
    {
        float4* Xs4 = (float4*)Xs;
        const float4* Xg4 = (const float4*)(X + (size_t)b * NN * FF);
        for (int i = tid; i < NN * FF / 4; i += NTHR) Xs4[i] = Xg4[i];
        if (tid < FF) Xs[NN * FF + tid] = 0.f;          // zero pad row 199
        const float* kg = Kg + (size_t)h * FF * NN;
        for (int i = tid; i < FF * KS_STRIDE; i += NTHR) {
            int f = i / KS_STRIDE, c = i - f * KS_STRIDE;
            Ks[i] = (c < NN) ? kg[f * NN + c] : 0.f;
        }
        float4* fcS4 = (float4*)fcS;
        const float4* fg4 = (const float4*)(FCg + (size_t)h * FF * UU);
        for (int i = tid; i < FF * UU / 4; i += NTHR) fcS4[i] = fg4[i];
    }
    __syncthreads();

    // ---- fused tile loop over m ----
    for (int m0 = 0; m0 < NN; m0 += MT) {
        // (0) stage AWT[m0:m0+64][0:200] -> Dt
        {
            const float4* awt4 = (const float4*)(g_AWT + (size_t)h * NN * NP);
            for (int i = tid; i < MT * 50; i += NTHR) {
                int r = i / 50, c = i - r * 50;
                float4 v = make_float4(0.f, 0.f, 0.f, 0.f);
                int m = m0 + r;
                if (m < NN) v = awt4[m * 50 + c];
                *(float4*)(Dt + r * DT_STRIDE + c * 4) = v;
            }
        }
        __syncthreads();

        // (1) feat[r][f] = sum_n AWT[r][n] * X[n][f]; thread = 1 row x 8 f
        {
            int r = row8, m = m0 + r;
            if (m < NN) {
                const float* ar = Dt + r * DT_STRIDE;
                float4 a0 = make_float4(0.f,0.f,0.f,0.f), a1 = a0;
                #pragma unroll 2
                for (int n0 = 0; n0 < NP; n0 += 4) {
                    float4 s = *(const float4*)(ar + n0);
                    #pragma unroll
                    for (int k = 0; k < 4; ++k) {
                        float sv = (k==0) ? s.x : (k==1) ? s.y : (k==2) ? s.z : s.w;
                        const float* xb = Xs + (n0 + k) * FF + jf4;
                        float4 v0 = *(const float4*)xb;
                        float4 v1 = *(const float4*)(xb + 32);
                        FMA8(a0, a1, sv, v0, v1)
                    }
                }
                *(float4*)(Ft + r * FT_STRIDE + jf4)      = a0;
                *(float4*)(Ft + r * FT_STRIDE + 32 + jf4) = a1;
            }
        }
        __syncthreads();

        // (2) dense[r][j] = sum_f feat[r][f]*K[f][j] + b1[j]; warp = 4 rows x 256 j
        {
            const int lane4 = lane * 4;
            const int c2 = 128 + lane4;
            const int c2l = (c2 <= 204) ? c2 : 204;     // clamped in-bounds (zeros)
            const int r0 = wid * 4;

            float4 bA, bB;
            bA.x = b1[h*NN + lane4];   bA.y = b1[h*NN + lane4+1];
            bA.z = b1[h*NN + lane4+2]; bA.w = b1[h*NN + lane4+3];
            bB.x = (c2   < NN) ? b1[h*NN + c2]   : 0.f;
            bB.y = (c2+1 < NN) ? b1[h*NN + c2+1] : 0.f;
            bB.z = (c2+2 < NN) ? b1[h*NN + c2+2] : 0.f;
            bB.w = (c2+3 < NN) ? b1[h*NN + c2+3] : 0.f;

            float4 acc[4][2];
            #pragma unroll
            for (int q = 0; q < 4; ++q) { acc[q][0] = bA; acc[q][1] = bB; }

            const float* ftb = Ft + r0 * FT_STRIDE;
            #pragma unroll 1
            for (int f0 = 0; f0 < FF; f0 += 4) {
                float4 s0 = *(const float4*)(ftb + 0*FT_STRIDE + f0);
                float4 s1 = *(const float4*)(ftb + 1*FT_STRIDE + f0);
                float4 s2 = *(const float4*)(ftb + 2*FT_STRIDE + f0);
                float4 s3 = *(const float4*)(ftb + 3*FT_STRIDE + f0);
                #pragma unroll
                for (int k = 0; k < 4; ++k) {
                    const float* kb = Ks + (f0 + k) * KS_STRIDE;
                    float4 k0 = *(const float4*)(kb + lane4);
                    float4 k1 = *(const float4*)(kb + c2l);
                    float w0 = (k==0)?s0.x:(k==1)?s0.y:(k==2)?s0.z:s0.w;
                    float w1 = (k==0)?s1.x:(k==1)?s1.y:(k==2)?s1.z:s1.w;
                    float w2 = (k==0)?s2.x:(k==1)?s2.y:(k==2)?s2.z:s2.w;
                    float w3 = (k==0)?s3.x:(k==1)?s3.y:(k==2)?s3.z:s3.w;
                    FMA8(acc[0][0], acc[0][1], w0, k0, k1)
                    FMA8(acc[1][0], acc[1][1], w1, k0, k1)
                    FMA8(acc[2][0], acc[2][1], w2, k0, k1)
                    FMA8(acc[3][0], acc[3][1], w3, k0, k1)
                }
            }
            #pragma unroll
            for (int q = 0; q < 4; ++q) {
                float* dr = Dt + (r0 + q) * DT_STRIDE;
                *(float4*)(dr + lane4) = acc[q][0];
                if (lane <= 16) {
                    *(float4*)(dr + c2) = acc[q][1];
                } else if (lane == 17) {            // cols 196..198
                    dr[196] = acc[q][1].x; dr[197] = acc[q][1].y; dr[198] = acc[q][1].z;
                }
            }
        }
        __syncthreads();

        // (3) adjacency-masked softmax; warp handles 4 rows
        #pragma unroll
        for (int rr = 0; rr < 4; ++rr) {
            int rl = wid * 4 + rr;
            int m  = m0 + rl;
            if (m < NN) {
                const float* Ar = A + (size_t)m * NN;
                float* dr = Dt + rl * DT_STRIDE;
                float v[7];
                float vmax = -INFINITY;
                #pragma unroll
                for (int t = 0; t < 7; ++t) {
                    int j = lane + 32 * t;
                    if (j < NN) {
                        float x = dr[j];
                        if (Ar[j] == 0.f) x -= 1e16f;
                        v[t] = x; vmax = fmaxf(vmax, x);
                    } else v[t] = -INFINITY;
                }
                for (int o = 16; o; o >>= 1) vmax = fmaxf(vmax, __shfl_xor_sync(0xffffffffu, vmax, o));
                float s = 0.f;
                #pragma unroll
                for (int t = 0; t < 7; ++t) {
                    int j = lane + 32 * t;
                    if (j < NN) { v[t] = __expf(v[t] - vmax); s += v[t]; }
                }
                for (int o = 16; o; o >>= 1) s += __shfl_xor_sync(0xffffffffu, s, o);
                float inv = 1.f / s;
                float* mout = out + ((size_t)b * NN + m) * COUT + HH * UU;
                #pragma unroll
                for (int t = 0; t < 7; ++t) {
                    int j = lane + 32 * t;
                    if (j < NN) {
                        float mv = v[t] * inv;
                        dr[j] = mv;
                        if (h == HH - 1) mout[j] = mv;
                    } else if (j < DT_STRIDE) {
                        dr[j] = 0.f;                // zero-pad cols 199..211 for step (4)
                    }
                }
            }
        }
        __syncthreads();

        // (4) node[r][f] = sum_j mask[r][j]*X[j][f]; thread = 1 row x 8 f
        {
            int r = row8, m = m0 + r;
            if (m < NN) {
                const float* mr = Dt + r * DT_STRIDE;
                float4 a0 = make_float4(0.f,0.f,0.f,0.f), a1 = a0;
                #pragma unroll 2
                for (int j0 = 0; j0 < NP; j0 += 4) {
                    float4 s = *(const float4*)(mr + j0);
                    #pragma unroll
                    for (int k = 0; k < 4; ++k) {
                        float sv = (k==0) ? s.x : (k==1) ? s.y : (k==2) ? s.z : s.w;
                        const float* xb = Xs + (j0 + k) * FF + jf4;
                        float4 v0 = *(const float4*)xb;
                        float4 v1 = *(const float4*)(xb + 32);
                        FMA8(a0, a1, sv, v0, v1)
                    }
                }
                *(float4*)(Nt + r * NT_STRIDE + jf4)      = a0;
                *(float4*)(Nt + r * NT_STRIDE + 32 + jf4) = a1;
            }
        }
        __syncthreads();

        // (5) out[r][u] = sum_f node[r][f]*fc[f][u] + b2[u]; thread = 1 row x 8 u
        {
            int r = row8, m = m0 + r;
            if (m < NN) {
                float4 a0, a1;
                a0.x = b2[h*UU + jf4];        a0.y = b2[h*UU + jf4 + 1];
                a0.z = b2[h*UU + jf4 + 2];    a0.w = b2[h*UU + jf4 + 3];
                a1.x = b2[h*UU + 32 + jf4];   a1.y = b2[h*UU + 32 + jf4 + 1];
                a1.z = b2[h*UU + 32 + jf4+2]; a1.w = b2[h*UU + 32 + jf4 + 3];
                const float* nr = Nt + r * NT_STRIDE;
                #pragma unroll 2
                for (int f0 = 0; f0 < FF; f0 += 4) {
                    float4 s = *(const float4*)(nr + f0);
                    #pragma unroll
                    for (int k = 0; k < 4; ++k) {
                        float sv = (k==0) ? s.x : (k==1) ? s.y : (k==2) ? s.z : s.w;
                        const float* fb = fcS + (f0 + k) * UU + jf4;
                        float4 v0 = *(const float4*)fb;
                        float4 v1 = *(const float4*)(fb + 32);
                        FMA8(a0, a1, sv, v0, v1)
                    }
                }
                float* orow = out + ((size_t)b * NN + m) * COUT + h * UU;
                orow[jf4]        = a0.x; orow[jf4 + 1]      = a0.y;
                orow[jf4 + 2]    = a0.z; orow[jf4 + 3]      = a0.w;
                orow[32 + jf4]   = a1.x; orow[32 + jf4 + 1] = a1.y;
                orow[32 + jf4+2] = a1.z; orow[32 + jf4 + 3] = a1.w;
            }
        }
        // no trailing sync needed: next tile's AWT staging writes Dt, whose last
        // readers (step 4) are fenced by the sync before step 5.
    }
}

extern "C" void kernel_launch(void* const* d_in, const int* in_sizes, int n_in,
                              void* d_out, int out_size) {
    const float* X  = (const float*)d_in[0];
    const float* A  = (const float*)d_in[1];
    const float* Kg = (const float*)d_in[2];
    const float* P  = (const float*)d_in[3];
    const float* FC = (const float*)d_in[4];
    const float* b1 = (const float*)d_in[5];
    const float* b2 = (const float*)d_in[6];
    for (int i = 0; i < n_in; ++i) {   // defensive remap: all sizes distinct
        int s = in_sizes[i];
        const float* p = (const float*)d_in[i];
        if      (s == BB * NN * FF) X  = p;
        else if (s == NN * NN)      A  = p;
        else if (s == HH * FF * NN) Kg = p;
        else if (s == HH * NN * NN) P  = p;
        else if (s == HH * FF * UU) FC = p;
        else if (s == HH * NN)      b1 = p;
        else if (s == HH * UU)      b2 = p;
    }

    awt_kernel<<<dim3(NN, HH), 128>>>(A, P);

    static int smem_set = 0;
    size_t smem = SMEM_FLOATS * sizeof(float);
    if (!smem_set) {
        cudaFuncSetAttribute(gc_kernel, cudaFuncAttributeMaxDynamicSharedMemorySize, (int)smem);
        smem_set = 1;
    }
    gc_kernel<<<dim3(BB, HH), NTHR, smem>>>(X, A, Kg, FC, b1, b2, (float*)d_out);
}

// round 7
// speedup vs baseline: 1.2059x; 1.2059x over previous
#include <cuda_runtime.h>
#include <math.h>

// Shapes fixed by setup_inputs: B=512, N=199, F=64, H=4, U=64
#define BB   512
#define NN   199
#define NP   200
#define FF   64
#define HH   4
#define UU   64
#define MT   64
#define COUT (HH*UU + NN)        // 455
#define NTHR 512

#define FT_STRIDE 68             // feat tile row stride (floats, mult of 4)
#define KS_STRIDE 208            // kernels row stride (zero-padded cols 199..207)
#define DT_STRIDE 212            // AWT-stage / dense / mask tile stride (mult of 4)
#define NT_STRIDE 68             // node tile stride

typedef unsigned long long u64;

// AWT[h][m][n] = A[n][m] * params[h][n][m], col 199 zero. 640KB, L2-resident.
__device__ float g_AWT[HH * NN * NP];

__global__ void awt_kernel(const float* __restrict__ A, const float* __restrict__ P) {
    int m = blockIdx.x, h = blockIdx.y;
    for (int n = threadIdx.x; n < NP; n += blockDim.x) {
        float v = 0.f;
        if (n < NN) v = A[n * NN + m] * P[((size_t)h * NN + n) * NN + m];
        g_AWT[((size_t)h * NN + m) * NP + n] = v;
    }
}

// ---- packed fp32x2 helpers (Blackwell FFMA2 path, PTX-only) ----
__device__ __forceinline__ void fma2(u64 &acc, u64 a, u64 b) {
    asm("fma.rn.f32x2 %0, %1, %2, %0;" : "+l"(acc) : "l"(a), "l"(b));
}
__device__ __forceinline__ u64 dup2(float v) {
    u64 r; unsigned u = __float_as_uint(v);
    asm("mov.b64 %0, {%1, %1};" : "=l"(r) : "r"(u));
    return r;
}
__device__ __forceinline__ u64 pack2(float a, float b) {
    u64 r; unsigned x = __float_as_uint(a), y = __float_as_uint(b);
    asm("mov.b64 %0, {%1, %2};" : "=l"(r) : "r"(x), "r"(y));
    return r;
}
__device__ __forceinline__ u64 add2(u64 a, u64 b) {
    u64 r; asm("add.rn.f32x2 %0, %1, %2;" : "=l"(r) : "l"(a), "l"(b));
    return r;
}
__device__ __forceinline__ float lo2(u64 a) {
    unsigned x, y; asm("mov.b64 {%0, %1}, %2;" : "=r"(x), "=r"(y) : "l"(a));
    return __uint_as_float(x);
}
__device__ __forceinline__ float hi2(u64 a) {
    unsigned x, y; asm("mov.b64 {%0, %1}, %2;" : "=r"(x), "=r"(y) : "l"(a));
    return __uint_as_float(y);
}

// 4 rows x 8 cols FFMA2 micro-step: acc[4][4] += dup(s_r) * (xa.x,xa.y,xc.x,xc.y)
#define STEP4x8(ACC, S0, S1, S2, S3, XA, XC) { u64 d_;                         \
    d_ = dup2(S0); fma2(ACC[0][0], d_, XA.x); fma2(ACC[0][1], d_, XA.y);       \
                   fma2(ACC[0][2], d_, XC.x); fma2(ACC[0][3], d_, XC.y);       \
    d_ = dup2(S1); fma2(ACC[1][0], d_, XA.x); fma2(ACC[1][1], d_, XA.y);       \
                   fma2(ACC[1][2], d_, XC.x); fma2(ACC[1][3], d_, XC.y);       \
    d_ = dup2(S2); fma2(ACC[2][0], d_, XA.x); fma2(ACC[2][1], d_, XA.y);       \
                   fma2(ACC[2][2], d_, XC.x); fma2(ACC[2][3], d_, XC.y);       \
    d_ = dup2(S3); fma2(ACC[3][0], d_, XA.x); fma2(ACC[3][1], d_, XA.y);       \
                   fma2(ACC[3][2], d_, XC.x); fma2(ACC[3][3], d_, XC.y); }

// SMEM (floats): Xs 12800 + Ft 4352 + Ks 13312 + fcS 4096 + Dt 13568 + Nt 4352 = 52480 -> 209920 B
// Bases (floats): 0, 12800, 17152, 30464, 34560, 48128 — all *4B multiples of 16.
#define SMEM_FLOATS (NP*FF + MT*FT_STRIDE + FF*KS_STRIDE + FF*UU + MT*DT_STRIDE + MT*NT_STRIDE)

__global__ __launch_bounds__(NTHR, 1)
void gc_kernel(const float* __restrict__ X, const float* __restrict__ A,
               const float* __restrict__ Kg, const float* __restrict__ FCg,
               const float* __restrict__ b1, const float* __restrict__ b2,
               float* __restrict__ out) {
    extern __shared__ float sm[];
    float* Xs  = sm;                        // [200][64]  X_b, row 199 zeroed
    float* Ft  = Xs + NP * FF;              // [64][68]   feat tile
    float* Ks  = Ft + MT * FT_STRIDE;       // [64][208]  kernels_h (cols >=199 zero)
    float* fcS = Ks + FF * KS_STRIDE;       // [64][64]
    float* Dt  = fcS + FF * UU;             // [64][212]  AWT stage -> dense -> mask
    float* Nt  = Dt + MT * DT_STRIDE;       // [64][68]   node tile

    const int b = blockIdx.x, h = blockIdx.y;
    const int tid  = threadIdx.x;
    const int lane = tid & 31, wid = tid >> 5;
    const int jf8  = (tid & 7) * 8;         // col base: 8 cols
    const int ksp  = tid >> 7;              // 4-way K-split group
    const int rq4  = ((tid >> 3) & 15) * 4; // row base within 64-row tile

    // ---- stage inputs ----
    {
        float4* Xs4 = (float4*)Xs;
        const float4* Xg4 = (const float4*)(X + (size_t)b * NN * FF);
        for (int i = tid; i < NN * FF / 4; i += NTHR) Xs4[i] = Xg4[i];
        if (tid < FF) Xs[NN * FF + tid] = 0.f;          // zero pad row 199
        const float* kg = Kg + (size_t)h * FF * NN;
        for (int i = tid; i < FF * KS_STRIDE; i += NTHR) {
            int f = i / KS_STRIDE, c = i - f * KS_STRIDE;
            Ks[i] = (c < NN) ? kg[f * NN + c] : 0.f;
        }
        float4* fcS4 = (float4*)fcS;
        const float4* fg4 = (const float4*)(FCg + (size_t)h * FF * UU);
        for (int i = tid; i < FF * UU / 4; i += NTHR) fcS4[i] = fg4[i];
    }
    __syncthreads();

    // ---- fused tile loop over m ----
    for (int m0 = 0; m0 < NN; m0 += MT) {
        // (0) stage AWT[m0:m0+64][0:200] -> Dt (rows >= NN zeroed)
        {
            const float4* awt4 = (const float4*)(g_AWT + (size_t)h * NN * NP);
            for (int i = tid; i < MT * 50; i += NTHR) {
                int r = i / 50, c = i - r * 50;
                float4 v = make_float4(0.f, 0.f, 0.f, 0.f);
                int m = m0 + r;
                if (m < NN) v = awt4[m * 50 + c];
                *(float4*)(Dt + r * DT_STRIDE + c * 4) = v;
            }
        }
        __syncthreads();

        // (1) feat[r][f] = sum_n AWT[r][n] * X[n][f]
        // thread = 4 rows x 8 cols; 4-way K-split (50 each); reduce into Ft
        {
            const float* a0 = Dt + (rq4 + 0) * DT_STRIDE;
            const float* a1 = Dt + (rq4 + 1) * DT_STRIDE;
            const float* a2 = Dt + (rq4 + 2) * DT_STRIDE;
            const float* a3 = Dt + (rq4 + 3) * DT_STRIDE;
            const int n0 = ksp * 50;

            u64 acc[4][4];
            #pragma unroll
            for (int r = 0; r < 4; ++r)
                #pragma unroll
                for (int k = 0; k < 4; ++k) acc[r][k] = 0ull;

            #pragma unroll 2
            for (int i = 0; i < 50; ++i) {
                int n = n0 + i;
                float s0 = a0[n], s1 = a1[n], s2 = a2[n], s3 = a3[n];
                const float* xb = Xs + n * FF + jf8;
                ulonglong2 xa = *(const ulonglong2*)xb;
                ulonglong2 xc = *(const ulonglong2*)(xb + 4);
                STEP4x8(acc, s0, s1, s2, s3, xa, xc)
            }
            #pragma unroll 1
            for (int round = 0; round < 4; ++round) {
                if (ksp == round) {
                    #pragma unroll
                    for (int r = 0; r < 4; ++r) {
                        u64* fr = (u64*)(Ft + (rq4 + r) * FT_STRIDE + jf8);
                        if (round == 0) {
                            fr[0] = acc[r][0]; fr[1] = acc[r][1];
                            fr[2] = acc[r][2]; fr[3] = acc[r][3];
                        } else {
                            fr[0] = add2(fr[0], acc[r][0]); fr[1] = add2(fr[1], acc[r][1]);
                            fr[2] = add2(fr[2], acc[r][2]); fr[3] = add2(fr[3], acc[r][3]);
                        }
                    }
                }
                __syncthreads();
            }
        }

        // (2) dense[r][j] = sum_f feat[r][f]*K[f][j] + b1[j]; warp = 4 rows x 256 j
        {
            const int lane4 = lane * 4;
            const int c2 = 128 + lane4;
            const int c2l = (c2 <= 204) ? c2 : 204;     // clamped in-bounds (zeros)
            const int r0 = wid * 4;

            u64 bA0 = pack2(b1[h*NN + lane4],     b1[h*NN + lane4 + 1]);
            u64 bA1 = pack2(b1[h*NN + lane4 + 2], b1[h*NN + lane4 + 3]);
            float bb0 = (c2     < NN) ? b1[h*NN + c2]     : 0.f;
            float bb1 = (c2 + 1 < NN) ? b1[h*NN + c2 + 1] : 0.f;
            float bb2 = (c2 + 2 < NN) ? b1[h*NN + c2 + 2] : 0.f;
            float bb3 = (c2 + 3 < NN) ? b1[h*NN + c2 + 3] : 0.f;
            u64 bB0 = pack2(bb0, bb1), bB1 = pack2(bb2, bb3);

            u64 acc[4][4];
            #pragma unroll
            for (int q = 0; q < 4; ++q) {
                acc[q][0] = bA0; acc[q][1] = bA1; acc[q][2] = bB0; acc[q][3] = bB1;
            }

            const float* ftb = Ft + r0 * FT_STRIDE;
            #pragma unroll 1
            for (int f0 = 0; f0 < FF; f0 += 4) {
                float4 s0 = *(const float4*)(ftb + 0*FT_STRIDE + f0);
                float4 s1 = *(const float4*)(ftb + 1*FT_STRIDE + f0);
                float4 s2 = *(const float4*)(ftb + 2*FT_STRIDE + f0);
                float4 s3 = *(const float4*)(ftb + 3*FT_STRIDE + f0);
                #pragma unroll
                for (int k = 0; k < 4; ++k) {
                    const float* kb = Ks + (f0 + k) * KS_STRIDE;
                    ulonglong2 ka = *(const ulonglong2*)(kb + lane4);
                    ulonglong2 kc = *(const ulonglong2*)(kb + c2l);
                    float w0 = (k==0)?s0.x:(k==1)?s0.y:(k==2)?s0.z:s0.w;
                    float w1 = (k==0)?s1.x:(k==1)?s1.y:(k==2)?s1.z:s1.w;
                    float w2 = (k==0)?s2.x:(k==1)?s2.y:(k==2)?s2.z:s2.w;
                    float w3 = (k==0)?s3.x:(k==1)?s3.y:(k==2)?s3.z:s3.w;
                    STEP4x8(acc, w0, w1, w2, w3, ka, kc)
                }
            }
            #pragma unroll
            for (int q = 0; q < 4; ++q) {
                float* dr = Dt + (r0 + q) * DT_STRIDE;
                float4 vA = make_float4(lo2(acc[q][0]), hi2(acc[q][0]),
                                        lo2(acc[q][1]), hi2(acc[q][1]));
                *(float4*)(dr + lane4) = vA;
                if (lane <= 16) {
                    float4 vB = make_float4(lo2(acc[q][2]), hi2(acc[q][2]),
                                            lo2(acc[q][3]), hi2(acc[q][3]));
                    *(float4*)(dr + c2) = vB;
                } else if (lane == 17) {            // cols 196..198
                    dr[196] = lo2(acc[q][2]); dr[197] = hi2(acc[q][2]);
                    dr[198] = lo2(acc[q][3]);
                }
            }
        }
        __syncthreads();

        // (3) adjacency-masked softmax; warp handles 4 rows
        #pragma unroll
        for (int rr = 0; rr < 4; ++rr) {
            int rl = wid * 4 + rr;
            int m  = m0 + rl;
            if (m < NN) {
                const float* Ar = A + (size_t)m * NN;
                float* dr = Dt + rl * DT_STRIDE;
                float v[7];
                float vmax = -INFINITY;
                #pragma unroll
                for (int t = 0; t < 7; ++t) {
                    int j = lane + 32 * t;
                    if (j < NN) {
                        float x = dr[j];
                        if (Ar[j] == 0.f) x -= 1e16f;
                        v[t] = x; vmax = fmaxf(vmax, x);
                    } else v[t] = -INFINITY;
                }
                for (int o = 16; o; o >>= 1) vmax = fmaxf(vmax, __shfl_xor_sync(0xffffffffu, vmax, o));
                float s = 0.f;
                #pragma unroll
                for (int t = 0; t < 7; ++t) {
                    int j = lane + 32 * t;
                    if (j < NN) { v[t] = __expf(v[t] - vmax); s += v[t]; }
                }
                for (int o = 16; o; o >>= 1) s += __shfl_xor_sync(0xffffffffu, s, o);
                float inv = 1.f / s;
                float* mout = out + ((size_t)b * NN + m) * COUT + HH * UU;
                #pragma unroll
                for (int t = 0; t < 7; ++t) {
                    int j = lane + 32 * t;
                    if (j < NN) {
                        float mv = v[t] * inv;
                        dr[j] = mv;
                        if (h == HH - 1) mout[j] = mv;
                    } else if (j < DT_STRIDE) {
                        dr[j] = 0.f;                // zero cols 199.. for step (4)
                    }
                }
            }
        }
        __syncthreads();

        // (4) node[r][f] = sum_j mask[r][j]*X[j][f]; same scheme as (1), out -> Nt
        {
            const float* a0 = Dt + (rq4 + 0) * DT_STRIDE;
            const float* a1 = Dt + (rq4 + 1) * DT_STRIDE;
            const float* a2 = Dt + (rq4 + 2) * DT_STRIDE;
            const float* a3 = Dt + (rq4 + 3) * DT_STRIDE;
            const int n0 = ksp * 50;

            u64 acc[4][4];
            #pragma unroll
            for (int r = 0; r < 4; ++r)
                #pragma unroll
                for (int k = 0; k < 4; ++k) acc[r][k] = 0ull;

            #pragma unroll 2
            for (int i = 0; i < 50; ++i) {
                int n = n0 + i;
                float s0 = a0[n], s1 = a1[n], s2 = a2[n], s3 = a3[n];
                const float* xb = Xs + n * FF + jf8;
                ulonglong2 xa = *(const ulonglong2*)xb;
                ulonglong2 xc = *(const ulonglong2*)(xb + 4);
                STEP4x8(acc, s0, s1, s2, s3, xa, xc)
            }
            #pragma unroll 1
            for (int round = 0; round < 4; ++round) {
                if (ksp == round) {
                    #pragma unroll
                    for (int r = 0; r < 4; ++r) {
                        u64* fr = (u64*)(Nt + (rq4 + r) * NT_STRIDE + jf8);
                        if (round == 0) {
                            fr[0] = acc[r][0]; fr[1] = acc[r][1];
                            fr[2] = acc[r][2]; fr[3] = acc[r][3];
                        } else {
                            fr[0] = add2(fr[0], acc[r][0]); fr[1] = add2(fr[1], acc[r][1]);
                            fr[2] = add2(fr[2], acc[r][2]); fr[3] = add2(fr[3], acc[r][3]);
                        }
                    }
                }
                __syncthreads();
            }
        }

        // (5) out[r][u] = sum_f node[r][f]*fc[f][u] + b2[u]; 128 threads, 4r x 8u each
        if (tid < 128) {
            u64 acc[4][4];
            u64 b0 = pack2(b2[h*UU + jf8],     b2[h*UU + jf8 + 1]);
            u64 b1p= pack2(b2[h*UU + jf8 + 2], b2[h*UU + jf8 + 3]);
            u64 b2p= pack2(b2[h*UU + jf8 + 4], b2[h*UU + jf8 + 5]);
            u64 b3p= pack2(b2[h*UU + jf8 + 6], b2[h*UU + jf8 + 7]);
            #pragma unroll
            for (int r = 0; r < 4; ++r) {
                acc[r][0] = b0; acc[r][1] = b1p; acc[r][2] = b2p; acc[r][3] = b3p;
            }
            const float* n0p = Nt + (rq4 + 0) * NT_STRIDE;
            const float* n1p = Nt + (rq4 + 1) * NT_STRIDE;
            const float* n2p = Nt + (rq4 + 2) * NT_STRIDE;
            const float* n3p = Nt + (rq4 + 3) * NT_STRIDE;
            #pragma unroll 2
            for (int f = 0; f < FF; ++f) {
                float s0 = n0p[f], s1 = n1p[f], s2 = n2p[f], s3 = n3p[f];
                const float* fb = fcS + f * UU + jf8;
                ulonglong2 fa = *(const ulonglong2*)fb;
                ulonglong2 fc = *(const ulonglong2*)(fb + 4);
                STEP4x8(acc, s0, s1, s2, s3, fa, fc)
            }
            #pragma unroll
            for (int r = 0; r < 4; ++r) {
                int m = m0 + rq4 + r;
                if (m < NN) {
                    float* orow = out + ((size_t)b * NN + m) * COUT + h * UU + jf8;
                    orow[0] = lo2(acc[r][0]); orow[1] = hi2(acc[r][0]);
                    orow[2] = lo2(acc[r][1]); orow[3] = hi2(acc[r][1]);
                    orow[4] = lo2(acc[r][2]); orow[5] = hi2(acc[r][2]);
                    orow[6] = lo2(acc[r][3]); orow[7] = hi2(acc[r][3]);
                }
            }
        }
        __syncthreads();
    }
}

extern "C" void kernel_launch(void* const* d_in, const int* in_sizes, int n_in,
                              void* d_out, int out_size) {
    const float* X  = (const float*)d_in[0];
    const float* A  = (const float*)d_in[1];
    const float* Kg = (const float*)d_in[2];
    const float* P  = (const float*)d_in[3];
    const float* FC = (const float*)d_in[4];
    const float* b1 = (const float*)d_in[5];
    const float* b2 = (const float*)d_in[6];
    for (int i = 0; i < n_in; ++i) {   // defensive remap: all sizes distinct
        int s = in_sizes[i];
        const float* p = (const float*)d_in[i];
        if      (s == BB * NN * FF) X  = p;
        else if (s == NN * NN)      A  = p;
        else if (s == HH * FF * NN) Kg = p;
        else if (s == HH * NN * NN) P  = p;
        else if (s == HH * FF * UU) FC = p;
        else if (s == HH * NN)      b1 = p;
        else if (s == HH * UU)      b2 = p;
    }

    awt_kernel<<<dim3(NN, HH), 128>>>(A, P);

    static int smem_set = 0;
    size_t smem = SMEM_FLOATS * sizeof(float);
    if (!smem_set) {
        cudaFuncSetAttribute(gc_kernel, cudaFuncAttributeMaxDynamicSharedMemorySize, (int)smem);
        smem_set = 1;
    }
    gc_kernel<<<dim3(BB, HH), NTHR, smem>>>(X, A, Kg, FC, b1, b2, (float*)d_out);
}